// round 4
// baseline (speedup 1.0000x reference)
#include <cuda_runtime.h>

#define IN_DIM   128
#define OUT_DIM  128
#define N_NEIGH  32
#define BATCH    8192
#define WPB      8
#define THREADS  (WPB * 32)
#define GRID     512                    // 2 batch-chunks per block, all resident
#define CHUNKS   (BATCH / (GRID * WPB)) // = 2

__device__ float g_v1[IN_DIM];
__device__ float g_v2[IN_DIM];
__device__ float g_c;

// ---------------- prep: v1 = W^T u1, v2 = W^T u2, c = b.(u1+u2) ----------------
// 1024 threads, 32 warps: thread (i, oc) loads 16 independent W values -> high MLP.
__global__ __launch_bounds__(1024)
void prep_kernel(const float* __restrict__ W_w,
                 const float* __restrict__ W_b,
                 const float* __restrict__ u) {
    const int t  = threadIdx.x;
    const int i  = t & 127;          // input-dim column
    const int oc = t >> 7;           // o-chunk 0..7 (16 o's each)

    __shared__ float p1[8][IN_DIM];
    __shared__ float p2[8][IN_DIM];

    float s1 = 0.f, s2 = 0.f;
    #pragma unroll
    for (int k = 0; k < 16; k++) {
        const int o = oc * 16 + k;
        const float w = W_w[o * IN_DIM + i];   // 16 independent loads in flight
        s1 += w * u[o];
        s2 += w * u[OUT_DIM + o];
    }
    p1[oc][i] = s1;
    p2[oc][i] = s2;
    __syncthreads();

    if (t < IN_DIM) {
        float a1 = 0.f, a2 = 0.f;
        #pragma unroll
        for (int k = 0; k < 8; k++) { a1 += p1[k][t]; a2 += p2[k][t]; }
        g_v1[t] = a1;
        g_v2[t] = a2;
    } else if (t < 160) {            // warp 4: bias term
        const int lane = t - 128;
        float c = 0.f;
        #pragma unroll
        for (int k = 0; k < 4; k++) {
            const int o = lane * 4 + k;
            c += W_b[o] * (u[o] + u[OUT_DIM + o]);
        }
        #pragma unroll
        for (int off = 16; off; off >>= 1)
            c += __shfl_xor_sync(0xffffffffu, c, off);
        if (lane == 0) g_c = c;
    }
}

// ---------------- main: one warp per batch element, 2 chunks per block ----------------
__global__ __launch_bounds__(THREADS, 6)
void gat_attn_kernel(const float* __restrict__ ai_sq,
                     const float* __restrict__ ai_sn,
                     float* __restrict__ out)
{
    __shared__ float spart[WPB][N_NEIGH][32];   // 32 KB partial-dot matrix
    __shared__ float sv1[IN_DIM], sv2[IN_DIM];
    __shared__ float sbeta[N_NEIGH][WPB + 1];
    __shared__ float sc;

    const int tid  = threadIdx.x;
    const int lane = tid & 31;
    const int warp = tid >> 5;

    if (tid < IN_DIM) { sv1[tid] = g_v1[tid]; sv2[tid] = g_v2[tid]; }
    if (tid == 0)     sc = g_c;
    __syncthreads();

    const float4 v1r = *reinterpret_cast<const float4*>(&sv1[lane * 4]);
    const float4 v2r = *reinterpret_cast<const float4*>(&sv2[lane * 4]);
    const float  cc  = sc;

    const size_t NSTR = (size_t)BATCH * (IN_DIM / 4);   // float4 stride between neighbors

    #pragma unroll
    for (int it = 0; it < CHUNKS; it++) {
        const int b0 = blockIdx.x * WPB + it * (GRID * WPB);
        const int b  = b0 + warp;

        // base term: ai_sq[b] . v1 + c
        const float4* sq = reinterpret_cast<const float4*>(ai_sq) + (size_t)b * (IN_DIM / 4);
        float4 a = __ldcs(&sq[lane]);
        float p = a.x * v1r.x + a.y * v1r.y + a.z * v1r.z + a.w * v1r.w;
        #pragma unroll
        for (int off = 16; off; off >>= 1) p += __shfl_xor_sync(0xffffffffu, p, off);
        const float base = p + cc;

        // 32 neighbor partial dots -> smem (short register lifetime => deep MLP)
        const float4* sn = reinterpret_cast<const float4*>(ai_sn)
                           + (size_t)b * (IN_DIM / 4) + lane;
        float* myrow = &spart[warp][0][0];
        #pragma unroll
        for (int n = 0; n < N_NEIGH; n++) {
            float4 x = __ldcs(&sn[(size_t)n * NSTR]);   // streaming, evict-first
            myrow[n * 32 + lane] = x.x * v2r.x + x.y * v2r.y + x.z * v2r.z + x.w * v2r.w;
        }
        __syncwarp();

        // lane l sums row l, rotated column order -> conflict-free
        float m = 0.f;
        const float* r = &spart[warp][lane][0];
        #pragma unroll
        for (int j = 0; j < 32; j++) m += r[(j + lane) & 31];
        m += base;

        // leaky_relu(0.01) -> exp -> 32-way softmax across lanes
        const float lr   = (m >= 0.f) ? m : 0.01f * m;
        const float beta = expf(lr);
        float s = beta;
        #pragma unroll
        for (int off = 16; off; off >>= 1) s += __shfl_xor_sync(0xffffffffu, s, off);

        sbeta[lane][warp] = beta / s;
        __syncthreads();

        // coalesced store: out[n, b0:b0+8] in 32B segments
        const int n = tid >> 3;
        const int j = tid & 7;
        out[(size_t)n * BATCH + b0 + j] = sbeta[n][j];
        __syncthreads();                 // sbeta safe for next chunk
    }
}

extern "C" void kernel_launch(void* const* d_in, const int* in_sizes, int n_in,
                              void* d_out, int out_size) {
    const float* ai_sq = (const float*)d_in[0];
    const float* ai_sn = (const float*)d_in[1];
    const float* W_w   = (const float*)d_in[2];
    const float* W_b   = (const float*)d_in[3];
    const float* u     = (const float*)d_in[4];
    float* out = (float*)d_out;

    prep_kernel<<<1, 1024>>>(W_w, W_b, u);
    gat_attn_kernel<<<GRID, THREADS>>>(ai_sq, ai_sn, out);
}

// round 9
// speedup vs baseline: 1.3347x; 1.3347x over previous
#include <cuda_runtime.h>

#define IN_DIM   128
#define OUT_DIM  128
#define N_NEIGH  32
#define BATCH    8192
#define WPB      8
#define THREADS  (WPB * 32)

__device__ float g_v1[IN_DIM];
__device__ float g_v2[IN_DIM];
__device__ float g_c;

// ---- prep: v1 = W^T u1, v2 = W^T u2, c = b.(u1+u2). 32 warps, 16 indep loads/thread ----
__global__ __launch_bounds__(1024)
void prep_kernel(const float* __restrict__ W_w,
                 const float* __restrict__ W_b,
                 const float* __restrict__ u) {
    const int t  = threadIdx.x;
    const int i  = t & 127;          // input-dim column
    const int oc = t >> 7;           // o-chunk 0..7

    __shared__ float p1[8][IN_DIM];
    __shared__ float p2[8][IN_DIM];

    float s1 = 0.f, s2 = 0.f;
    #pragma unroll
    for (int k = 0; k < 16; k++) {
        const int o = oc * 16 + k;
        const float w = W_w[o * IN_DIM + i];
        s1 += w * u[o];
        s2 += w * u[OUT_DIM + o];
    }
    p1[oc][i] = s1;
    p2[oc][i] = s2;
    __syncthreads();

    if (t < IN_DIM) {
        float a1 = 0.f, a2 = 0.f;
        #pragma unroll
        for (int k = 0; k < 8; k++) { a1 += p1[k][t]; a2 += p2[k][t]; }
        g_v1[t] = a1;
        g_v2[t] = a2;
    } else if (t < 160) {            // warp 4: bias term
        const int lane = t - 128;
        float c = 0.f;
        #pragma unroll
        for (int k = 0; k < 4; k++) {
            const int o = lane * 4 + k;
            c += W_b[o] * (u[o] + u[OUT_DIM + o]);
        }
        #pragma unroll
        for (int off = 16; off; off >>= 1)
            c += __shfl_xor_sync(0xffffffffu, c, off);
        if (lane == 0) g_c = c;
    }
}

// ---- main: one warp per batch element, register-resident partials (proven best) ----
__global__ __launch_bounds__(THREADS)
void gat_attn_kernel(const float* __restrict__ ai_sq,
                     const float* __restrict__ ai_sn,
                     float* __restrict__ out)
{
    const int tid  = threadIdx.x;
    const int lane = tid & 31;
    const int warp = tid >> 5;

    __shared__ float sv1[IN_DIM];
    __shared__ float sv2[IN_DIM];
    __shared__ float sc;
    __shared__ float sbeta[N_NEIGH][WPB + 1];   // padded output staging
    if (tid < IN_DIM) { sv1[tid] = g_v1[tid]; sv2[tid] = g_v2[tid]; }
    if (tid == 0)     sc = g_c;
    __syncthreads();

    const int b0 = blockIdx.x * WPB;
    const int b  = b0 + warp;

    // Lane l owns input-dim slice [4l, 4l+4)
    const float4 v1r = *reinterpret_cast<const float4*>(&sv1[lane * 4]);
    const float4 v2r = *reinterpret_cast<const float4*>(&sv2[lane * 4]);

    // base term: ai_sq[b] . v1 + c
    const float4* sq = reinterpret_cast<const float4*>(ai_sq) + (size_t)b * (IN_DIM / 4);
    float4 a = __ldcs(&sq[lane]);
    float p = a.x * v1r.x + a.y * v1r.y + a.z * v1r.z + a.w * v1r.w;
    #pragma unroll
    for (int o = 16; o; o >>= 1) p += __shfl_xor_sync(0xffffffffu, p, o);
    const float base = p + sc;

    // 32 neighbor partial dots, register-resident (load-first => deep MLP)
    const size_t NSTR = (size_t)BATCH * (IN_DIM / 4);
    const float4* sn = reinterpret_cast<const float4*>(ai_sn)
                       + (size_t)b * (IN_DIM / 4) + lane;

    float v[N_NEIGH];
    #pragma unroll
    for (int n = 0; n < N_NEIGH; n++) {
        float4 x = __ldcs(&sn[(size_t)n * NSTR]);   // streaming, evict-first
        v[n] = x.x * v2r.x + x.y * v2r.y + x.z * v2r.z + x.w * v2r.w;
    }

    // recursive-halving 32x32 transpose-reduce: 31 shuffles total.
    // After this, lane l holds the full cross-lane sum of v[l].
    #pragma unroll
    for (int off = 16; off; off >>= 1) {
        const bool hi = (lane & off) != 0;
        #pragma unroll
        for (int j = 0; j < off; j++) {
            float keep = hi ? v[j + off] : v[j];
            float send = hi ? v[j]       : v[j + off];
            v[j] = keep + __shfl_xor_sync(0xffffffffu, send, off);
        }
    }
    float m = v[0] + base;

    // leaky_relu(0.01) -> exp -> 32-way softmax across lanes
    const float lr   = (m >= 0.f) ? m : 0.01f * m;
    const float beta = expf(lr);
    float s = beta;
    #pragma unroll
    for (int o = 16; o; o >>= 1) s += __shfl_xor_sync(0xffffffffu, s, o);

    sbeta[lane][warp] = beta / s;
    __syncthreads();

    // coalesced store: out[n, b0:b0+8] in contiguous 32B segments
    const int n = tid >> 3;
    const int j = tid & 7;
    out[(size_t)n * BATCH + b0 + j] = sbeta[n][j];
}

extern "C" void kernel_launch(void* const* d_in, const int* in_sizes, int n_in,
                              void* d_out, int out_size) {
    const float* ai_sq = (const float*)d_in[0];
    const float* ai_sn = (const float*)d_in[1];
    const float* W_w   = (const float*)d_in[2];
    const float* W_b   = (const float*)d_in[3];
    const float* u     = (const float*)d_in[4];
    float* out = (float*)d_out;

    prep_kernel<<<1, 1024>>>(W_w, W_b, u);
    gat_attn_kernel<<<BATCH / WPB, THREADS>>>(ai_sq, ai_sn, out);
}

// round 11
// speedup vs baseline: 1.4087x; 1.0554x over previous
#include <cuda_runtime.h>

#define IN_DIM   128
#define OUT_DIM  128
#define N_NEIGH  32
#define BATCH    8192
#define WPB      8
#define THREADS  (WPB * 32)

__device__ float g_v1[IN_DIM];
__device__ float g_v2[IN_DIM];
__device__ float g_c;

// ---- prep: v1 = W^T u1, v2 = W^T u2, c = b.(u1+u2). 32 warps, 16 indep loads/thread ----
__global__ __launch_bounds__(1024)
void prep_kernel(const float* __restrict__ W_w,
                 const float* __restrict__ W_b,
                 const float* __restrict__ u) {
    const int t  = threadIdx.x;
    const int i  = t & 127;
    const int oc = t >> 7;

    __shared__ float p1[8][IN_DIM];
    __shared__ float p2[8][IN_DIM];

    float s1 = 0.f, s2 = 0.f;
    #pragma unroll
    for (int k = 0; k < 16; k++) {
        const int o = oc * 16 + k;
        const float w = W_w[o * IN_DIM + i];
        s1 += w * u[o];
        s2 += w * u[OUT_DIM + o];
    }
    p1[oc][i] = s1;
    p2[oc][i] = s2;
    __syncthreads();

    if (t < IN_DIM) {
        float a1 = 0.f, a2 = 0.f;
        #pragma unroll
        for (int k = 0; k < 8; k++) { a1 += p1[k][t]; a2 += p2[k][t]; }
        g_v1[t] = a1;
        g_v2[t] = a2;
    } else if (t < 160) {
        const int lane = t - 128;
        float c = 0.f;
        #pragma unroll
        for (int k = 0; k < 4; k++) {
            const int o = lane * 4 + k;
            c += W_b[o] * (u[o] + u[OUT_DIM + o]);
        }
        #pragma unroll
        for (int off = 16; off; off >>= 1)
            c += __shfl_xor_sync(0xffffffffu, c, off);
        if (lane == 0) g_c = c;
    }
}

// ---- main: one warp per batch elem; 4 chunks x 8 batched loads (MLP=8) ----
__global__ __launch_bounds__(THREADS, 4)
void gat_attn_kernel(const float* __restrict__ ai_sq,
                     const float* __restrict__ ai_sn,
                     float* __restrict__ out)
{
    const int tid  = threadIdx.x;
    const int lane = tid & 31;
    const int warp = tid >> 5;

    __shared__ float sv1[IN_DIM];
    __shared__ float sv2[IN_DIM];
    __shared__ float sc;
    __shared__ float sbeta[N_NEIGH][WPB + 1];
    if (tid < IN_DIM) { sv1[tid] = g_v1[tid]; sv2[tid] = g_v2[tid]; }
    if (tid == 0)     sc = g_c;
    __syncthreads();

    const int b0 = blockIdx.x * WPB;
    const int b  = b0 + warp;

    const float4 v1r = *reinterpret_cast<const float4*>(&sv1[lane * 4]);
    const float4 v2r = *reinterpret_cast<const float4*>(&sv2[lane * 4]);

    // base term: ai_sq[b] . v1 + c (load issued early, overlaps chunk 0)
    const float4* sq = reinterpret_cast<const float4*>(ai_sq) + (size_t)b * (IN_DIM / 4);
    float4 a = __ldcs(&sq[lane]);
    float p0 = a.x * v1r.x + a.y * v1r.y + a.z * v1r.z + a.w * v1r.w;
    #pragma unroll
    for (int o = 16; o; o >>= 1) p0 += __shfl_xor_sync(0xffffffffu, p0, o);
    const float base = p0 + sc;

    const size_t NSTR = (size_t)BATCH * (IN_DIM / 4);   // float4 stride between neighbors
    const float4* sn = reinterpret_cast<const float4*>(ai_sn)
                       + (size_t)b * (IN_DIM / 4) + lane;

    float m = 0.f;                      // lane l will hold mult[l, b]
    #pragma unroll 1
    for (int c = 0; c < 4; c++) {       // 4 chunks of 8 neighbors
        // batch 8 independent LDG.128 -> MLP 8
        float4 x[8];
        #pragma unroll
        for (int k = 0; k < 8; k++)
            x[k] = __ldcs(&sn[(size_t)(c * 8 + k) * NSTR]);

        float p[8];
        #pragma unroll
        for (int k = 0; k < 8; k++)
            p[k] = x[k].x * v2r.x + x[k].y * v2r.y + x[k].z * v2r.z + x[k].w * v2r.w;

        // 8-array halving transpose-reduce (lane l ends with array (l>>2)&7)
        #pragma unroll
        for (int j = 0; j < 4; j++) {
            const bool hi = (lane & 16) != 0;
            float keep = hi ? p[j + 4] : p[j];
            float send = hi ? p[j]     : p[j + 4];
            p[j] = keep + __shfl_xor_sync(0xffffffffu, send, 16);
        }
        #pragma unroll
        for (int j = 0; j < 2; j++) {
            const bool hi = (lane & 8) != 0;
            float keep = hi ? p[j + 2] : p[j];
            float send = hi ? p[j]     : p[j + 2];
            p[j] = keep + __shfl_xor_sync(0xffffffffu, send, 8);
        }
        {
            const bool hi = (lane & 4) != 0;
            float keep = hi ? p[1] : p[0];
            float send = hi ? p[0] : p[1];
            p[0] = keep + __shfl_xor_sync(0xffffffffu, send, 4);
        }
        p[0] += __shfl_xor_sync(0xffffffffu, p[0], 2);
        p[0] += __shfl_xor_sync(0xffffffffu, p[0], 1);

        // lane l wants neighbor l = 8c + (l&7); its total sits on lane (l&7)<<2
        const float val = __shfl_sync(0xffffffffu, p[0], (lane & 7) << 2);
        if ((lane >> 3) == c) m = val;
    }
    m += base;

    // leaky_relu(0.01) -> exp -> 32-way softmax across lanes
    const float lr   = (m >= 0.f) ? m : 0.01f * m;
    const float beta = expf(lr);
    float s = beta;
    #pragma unroll
    for (int o = 16; o; o >>= 1) s += __shfl_xor_sync(0xffffffffu, s, o);

    sbeta[lane][warp] = beta / s;
    __syncthreads();

    // coalesced store: out[n, b0:b0+8] in contiguous 32B segments
    const int n = tid >> 3;
    const int j = tid & 7;
    out[(size_t)n * BATCH + b0 + j] = sbeta[n][j];
}

extern "C" void kernel_launch(void* const* d_in, const int* in_sizes, int n_in,
                              void* d_out, int out_size) {
    const float* ai_sq = (const float*)d_in[0];
    const float* ai_sn = (const float*)d_in[1];
    const float* W_w   = (const float*)d_in[2];
    const float* W_b   = (const float*)d_in[3];
    const float* u     = (const float*)d_in[4];
    float* out = (float*)d_out;

    prep_kernel<<<1, 1024>>>(W_w, W_b, u);
    gat_attn_kernel<<<BATCH / WPB, THREADS>>>(ai_sq, ai_sn, out);
}